// round 1
// baseline (speedup 1.0000x reference)
#include <cuda_runtime.h>
#include <cuda_bf16.h>

#define NG   2048
#define W_IMG 128
#define H_IMG 128
#define HW   16384
#define SEG  8
#define GPER (NG/SEG)   // 256 gaussians per segment

// ---------------- scratch (static device globals; no dynamic alloc) ----------
__device__ float4 g_p0[NG], g_p1[NG];   // unsorted packed params
__device__ float  g_p2[NG], g_tz[NG];
__device__ float4 g_s0[NG], g_s1[NG];   // depth-sorted packed params
__device__ float  g_s2[NG];
__device__ float4 g_part[SEG * HW];     // per-(segment,pixel) partial (r,g,b,T)

__device__ __forceinline__ float ex2(float x) {
    float y;
    asm("ex2.approx.f32 %0, %1;" : "=f"(y) : "f"(x));
    return y;
}

// ---------------- 1) per-gaussian preprocess --------------------------------
__global__ void k_prep(const float* __restrict__ pts, const float* __restrict__ scl,
                       const float* __restrict__ col, const float* __restrict__ opa,
                       const float* __restrict__ rot, const float* __restrict__ view,
                       const float* __restrict__ proj, float* __restrict__ out)
{
    int i = blockIdx.x * 256 + threadIdx.x;
    if (i >= NG) return;

    float v[16], pr[16];
#pragma unroll
    for (int k = 0; k < 16; k++) v[k]  = view[k];
#pragma unroll
    for (int k = 0; k < 16; k++) pr[k] = proj[k];

    float p0 = pts[3*i], p1 = pts[3*i+1], p2 = pts[3*i+2];

    // camera-space point
    float t0 = v[0]*p0 + v[1]*p1 + v[2]*p2  + v[3];
    float t1 = v[4]*p0 + v[5]*p1 + v[6]*p2  + v[7];
    float tz = v[8]*p0 + v[9]*p1 + v[10]*p2 + v[11];

    // quaternion -> rotation
    float q0 = rot[4*i], q1 = rot[4*i+1], q2 = rot[4*i+2], q3 = rot[4*i+3];
    float qn = rsqrtf(q0*q0 + q1*q1 + q2*q2 + q3*q3);
    q0 *= qn; q1 *= qn; q2 *= qn; q3 *= qn;
    float R0 = 1.f - 2.f*(q2*q2 + q3*q3), R1 = 2.f*(q1*q2 - q0*q3), R2 = 2.f*(q1*q3 + q0*q2);
    float R3 = 2.f*(q1*q2 + q0*q3), R4 = 1.f - 2.f*(q1*q1 + q3*q3), R5 = 2.f*(q2*q3 - q0*q1);
    float R6 = 2.f*(q1*q3 - q0*q2), R7 = 2.f*(q2*q3 + q0*q1), R8 = 1.f - 2.f*(q1*q1 + q2*q2);

    float s0 = expf(scl[3*i]), s1 = expf(scl[3*i+1]), s2 = expf(scl[3*i+2]);
    // M = R * s (column scaling)
    float M0 = R0*s0, M1 = R1*s1, M2 = R2*s2;
    float M3 = R3*s0, M4 = R4*s1, M5 = R5*s2;
    float M6 = R6*s0, M7 = R7*s1, M8 = R8*s2;

    const float fx = 64.f, fy = 64.f;      // W/(2*TANX), H/(2*TANY)
    float invz = 1.0f / tz;
    float txz = fminf(fmaxf(t0*invz, -1.3f), 1.3f) * tz;
    float tyz = fminf(fmaxf(t1*invz, -1.3f), 1.3f) * tz;
    float J00 = fx*invz, J02 = -fx*txz*invz*invz;
    float J11 = fy*invz, J12 = -fy*tyz*invz*invz;

    // Tm = J @ view[:3,:3]
    float T00 = J00*v[0] + J02*v[8],  T01 = J00*v[1] + J02*v[9],  T02 = J00*v[2] + J02*v[10];
    float T10 = J11*v[4] + J12*v[8],  T11 = J11*v[5] + J12*v[9],  T12 = J11*v[6] + J12*v[10];

    // X = Tm @ M  (2x3);  cov2d = X X^T
    float X00 = T00*M0 + T01*M3 + T02*M6;
    float X01 = T00*M1 + T01*M4 + T02*M7;
    float X02 = T00*M2 + T01*M5 + T02*M8;
    float X10 = T10*M0 + T11*M3 + T12*M6;
    float X11 = T10*M1 + T11*M4 + T12*M7;
    float X12 = T10*M2 + T11*M5 + T12*M8;

    float a = X00*X00 + X01*X01 + X02*X02 + 0.3f;
    float b = X00*X10 + X01*X11 + X02*X12;
    float c = X10*X10 + X11*X11 + X12*X12 + 0.3f;

    float det   = a*c - b*b;
    bool  valid = (tz > 0.2f) && (det > 0.0f);
    float det_s = (det > 0.0f) ? det : 1.0f;
    float idet  = 1.0f / det_s;

    const float L2E = 1.4426950408889634f;
    // power(log2) = A2*dx^2 + C2*dy^2 + Bq*dx*dy
    float A2 = -0.5f * c * idet * L2E;
    float C2 = -0.5f * a * idet * L2E;
    float Bq =         b * idet * L2E;   // = -cB * L2E

    float mid   = 0.5f * (a + c);
    float lam   = mid + sqrtf(fmaxf(mid*mid - det, 0.1f));
    float radii = valid ? ceilf(3.0f * sqrtf(lam)) : 0.0f;

    // full = proj @ view; rows 0, 1, 3
    float fr0[4], fr1[4], fr3[4];
#pragma unroll
    for (int cc = 0; cc < 4; cc++) {
        fr0[cc] = pr[0]*v[cc]  + pr[1]*v[4+cc]  + pr[2]*v[8+cc]  + pr[3]*v[12+cc];
        fr1[cc] = pr[4]*v[cc]  + pr[5]*v[4+cc]  + pr[6]*v[8+cc]  + pr[7]*v[12+cc];
        fr3[cc] = pr[12]*v[cc] + pr[13]*v[4+cc] + pr[14]*v[8+cc] + pr[15]*v[12+cc];
    }
    float ph0 = fr0[0]*p0 + fr0[1]*p1 + fr0[2]*p2 + fr0[3];
    float ph1 = fr1[0]*p0 + fr1[1]*p1 + fr1[2]*p2 + fr1[3];
    float ph3 = fr3[0]*p0 + fr3[1]*p1 + fr3[2]*p2 + fr3[3];
    float pwn = 1.0f / (ph3 + 1e-7f);
    float px  = ((ph0*pwn + 1.0f) * (float)W_IMG - 1.0f) * 0.5f;
    float py  = ((ph1*pwn + 1.0f) * (float)H_IMG - 1.0f) * 0.5f;

    float op = valid ? (1.0f / (1.0f + expf(-opa[i]))) : 0.0f;
    float cr = 1.0f / (1.0f + expf(-col[3*i]));
    float cg = 1.0f / (1.0f + expf(-col[3*i+1]));
    float cb = 1.0f / (1.0f + expf(-col[3*i+2]));

    g_p0[i] = make_float4(px, py, A2, Bq);
    g_p1[i] = make_float4(C2, op, cr, cg);
    g_p2[i] = cb;
    g_tz[i] = tz;

    out[3*HW + i]      = radii;
    out[3*HW + NG + i] = tz;
}

// ---------------- 2) bitonic argsort by depth + gather ----------------------
__global__ void k_sort()
{
    __shared__ float sk[NG];
    __shared__ int   sv[NG];
    int tid = threadIdx.x;                    // 1024 threads
    for (int i = tid; i < NG; i += 1024) { sk[i] = g_tz[i]; sv[i] = i; }

    for (int k = 2; k <= NG; k <<= 1) {
        for (int j = k >> 1; j > 0; j >>= 1) {
            __syncthreads();
            for (int i = tid; i < NG; i += 1024) {
                int ixj = i ^ j;
                if (ixj > i) {
                    bool up = ((i & k) == 0);
                    float ka = sk[i], kb = sk[ixj];
                    if ((ka > kb) == up) {
                        sk[i] = kb; sk[ixj] = ka;
                        int tv = sv[i]; sv[i] = sv[ixj]; sv[ixj] = tv;
                    }
                }
            }
        }
    }
    __syncthreads();
    for (int i = tid; i < NG; i += 1024) {
        int src = sv[i];
        g_s0[i] = g_p0[src];
        g_s1[i] = g_p1[src];
        g_s2[i] = g_p2[src];
    }
}

// ---------------- 3) segmented blend ----------------------------------------
__global__ void __launch_bounds__(256) k_blend()
{
    __shared__ float4 sh0[GPER], sh1[GPER];
    __shared__ float  sh2[GPER];
    int tid  = threadIdx.x;                 // 256
    int seg  = blockIdx.y;
    int base = seg * GPER;
    sh0[tid] = g_s0[base + tid];
    sh1[tid] = g_s1[base + tid];
    sh2[tid] = g_s2[base + tid];
    __syncthreads();

    int   pix = blockIdx.x * 256 + tid;
    float x = (float)(pix & (W_IMG - 1));
    float y = (float)(pix >> 7);

    float r = 0.f, g = 0.f, b = 0.f, T = 1.f;
#pragma unroll 4
    for (int n = 0; n < GPER; n++) {
        float4 a0 = sh0[n];
        float4 a1 = sh1[n];
        float  cb = sh2[n];
        float dx = x - a0.x;
        float dy = y - a0.y;
        float pw = fmaf(a0.z*dx, dx, fmaf(a1.x*dy, dy, (a0.w*dx)*dy));
        float e  = ex2(pw);
        float al = fminf(a1.y * e, 0.99f);
        float w  = ((pw <= 0.0f) && (al >= 0.0039215686f)) ? T * al : 0.0f;
        r = fmaf(w, a1.z, r);
        g = fmaf(w, a1.w, g);
        b = fmaf(w, cb,   b);
        T -= w;
    }
    g_part[seg * HW + pix] = make_float4(r, g, b, T);
}

// ---------------- 4) combine segment partials -------------------------------
__global__ void k_combine(float* __restrict__ out)
{
    int p = blockIdx.x * 256 + threadIdx.x;
    float T = 1.f, r = 0.f, g = 0.f, b = 0.f;
#pragma unroll
    for (int s = 0; s < SEG; s++) {
        float4 f = g_part[s * HW + p];
        r = fmaf(T, f.x, r);
        g = fmaf(T, f.y, g);
        b = fmaf(T, f.z, b);
        T *= f.w;
    }
    out[p]        = r;
    out[HW + p]   = g;
    out[2*HW + p] = b;
}

// ---------------- launch -----------------------------------------------------
extern "C" void kernel_launch(void* const* d_in, const int* in_sizes, int n_in,
                              void* d_out, int out_size)
{
    const float* pts  = (const float*)d_in[0];
    const float* scl  = (const float*)d_in[1];
    const float* col  = (const float*)d_in[2];
    const float* opa  = (const float*)d_in[3];
    const float* rot  = (const float*)d_in[4];
    const float* view = (const float*)d_in[5];
    const float* proj = (const float*)d_in[6];
    float* out = (float*)d_out;

    k_prep<<<NG/256, 256>>>(pts, scl, col, opa, rot, view, proj, out);
    k_sort<<<1, 1024>>>();
    k_blend<<<dim3(HW/256, SEG), 256>>>();
    k_combine<<<HW/256, 256>>>(out);
}

// round 2
// speedup vs baseline: 1.5365x; 1.5365x over previous
#include <cuda_runtime.h>
#include <cuda_bf16.h>

#define NG    2048
#define W_IMG 128
#define H_IMG 128
#define HW    16384
#define NCHUNK 8          // 2048 / 256 depth chunks

// ---------------- scratch (static device globals) ----------------------------
__device__ float4 g_p0[NG], g_p1[NG];          // unsorted packed params
__device__ float2 g_p2[NG];                    // (cb, cullR)
__device__ unsigned long long g_key[NG];       // monotone depth key | index
__device__ float4 g_s0[NG], g_s1[NG];          // depth-sorted
__device__ float2 g_s2[NG];

__device__ __forceinline__ float ex2(float x) {
    float y;
    asm("ex2.approx.f32 %0, %1;" : "=f"(y) : "f"(x));
    return y;
}

// monotone map float -> uint (total order matches float <)
__device__ __forceinline__ unsigned fkey(float f) {
    unsigned u = __float_as_uint(f);
    return (u & 0x80000000u) ? ~u : (u | 0x80000000u);
}

// ---------------- 1) per-gaussian preprocess --------------------------------
__global__ void k_prep(const float* __restrict__ pts, const float* __restrict__ scl,
                       const float* __restrict__ col, const float* __restrict__ opa,
                       const float* __restrict__ rot, const float* __restrict__ view,
                       const float* __restrict__ proj, float* __restrict__ out)
{
    int i = blockIdx.x * 256 + threadIdx.x;
    if (i >= NG) return;

    float v[16], pr[16];
#pragma unroll
    for (int k = 0; k < 16; k++) v[k]  = view[k];
#pragma unroll
    for (int k = 0; k < 16; k++) pr[k] = proj[k];

    float p0 = pts[3*i], p1 = pts[3*i+1], p2 = pts[3*i+2];

    // camera-space point
    float t0 = v[0]*p0 + v[1]*p1 + v[2]*p2  + v[3];
    float t1 = v[4]*p0 + v[5]*p1 + v[6]*p2  + v[7];
    float tz = v[8]*p0 + v[9]*p1 + v[10]*p2 + v[11];

    // quaternion -> rotation
    float q0 = rot[4*i], q1 = rot[4*i+1], q2 = rot[4*i+2], q3 = rot[4*i+3];
    float qn = rsqrtf(q0*q0 + q1*q1 + q2*q2 + q3*q3);
    q0 *= qn; q1 *= qn; q2 *= qn; q3 *= qn;
    float R0 = 1.f - 2.f*(q2*q2 + q3*q3), R1 = 2.f*(q1*q2 - q0*q3), R2 = 2.f*(q1*q3 + q0*q2);
    float R3 = 2.f*(q1*q2 + q0*q3), R4 = 1.f - 2.f*(q1*q1 + q3*q3), R5 = 2.f*(q2*q3 - q0*q1);
    float R6 = 2.f*(q1*q3 - q0*q2), R7 = 2.f*(q2*q3 + q0*q1), R8 = 1.f - 2.f*(q1*q1 + q2*q2);

    float s0 = expf(scl[3*i]), s1 = expf(scl[3*i+1]), s2 = expf(scl[3*i+2]);
    float M0 = R0*s0, M1 = R1*s1, M2 = R2*s2;
    float M3 = R3*s0, M4 = R4*s1, M5 = R5*s2;
    float M6 = R6*s0, M7 = R7*s1, M8 = R8*s2;

    const float fx = 64.f, fy = 64.f;
    float invz = 1.0f / tz;
    float txz = fminf(fmaxf(t0*invz, -1.3f), 1.3f) * tz;
    float tyz = fminf(fmaxf(t1*invz, -1.3f), 1.3f) * tz;
    float J00 = fx*invz, J02 = -fx*txz*invz*invz;
    float J11 = fy*invz, J12 = -fy*tyz*invz*invz;

    float T00 = J00*v[0] + J02*v[8],  T01 = J00*v[1] + J02*v[9],  T02 = J00*v[2] + J02*v[10];
    float T10 = J11*v[4] + J12*v[8],  T11 = J11*v[5] + J12*v[9],  T12 = J11*v[6] + J12*v[10];

    float X00 = T00*M0 + T01*M3 + T02*M6;
    float X01 = T00*M1 + T01*M4 + T02*M7;
    float X02 = T00*M2 + T01*M5 + T02*M8;
    float X10 = T10*M0 + T11*M3 + T12*M6;
    float X11 = T10*M1 + T11*M4 + T12*M7;
    float X12 = T10*M2 + T11*M5 + T12*M8;

    float a = X00*X00 + X01*X01 + X02*X02 + 0.3f;
    float b = X00*X10 + X01*X11 + X02*X12;
    float c = X10*X10 + X11*X11 + X12*X12 + 0.3f;

    float det   = a*c - b*b;
    bool  valid = (tz > 0.2f) && (det > 0.0f);
    float det_s = (det > 0.0f) ? det : 1.0f;
    float idet  = 1.0f / det_s;

    const float L2E = 1.4426950408889634f;
    float A2 = -0.5f * c * idet * L2E;
    float C2 = -0.5f * a * idet * L2E;
    float Bq =         b * idet * L2E;

    float mid   = 0.5f * (a + c);
    float lam   = mid + sqrtf(fmaxf(mid*mid - det, 0.1f));
    float radii = valid ? ceilf(3.0f * sqrtf(lam)) : 0.0f;
    // exact cull radius: alpha<1/255 guaranteed beyond 3.3292*sqrt(lam) since op<1
    float cullR = valid ? 3.3294f * sqrtf(lam) : 0.0f;

    float fr0[4], fr1[4], fr3[4];
#pragma unroll
    for (int cc = 0; cc < 4; cc++) {
        fr0[cc] = pr[0]*v[cc]  + pr[1]*v[4+cc]  + pr[2]*v[8+cc]  + pr[3]*v[12+cc];
        fr1[cc] = pr[4]*v[cc]  + pr[5]*v[4+cc]  + pr[6]*v[8+cc]  + pr[7]*v[12+cc];
        fr3[cc] = pr[12]*v[cc] + pr[13]*v[4+cc] + pr[14]*v[8+cc] + pr[15]*v[12+cc];
    }
    float ph0 = fr0[0]*p0 + fr0[1]*p1 + fr0[2]*p2 + fr0[3];
    float ph1 = fr1[0]*p0 + fr1[1]*p1 + fr1[2]*p2 + fr1[3];
    float ph3 = fr3[0]*p0 + fr3[1]*p1 + fr3[2]*p2 + fr3[3];
    float pwn = 1.0f / (ph3 + 1e-7f);
    float px  = ((ph0*pwn + 1.0f) * (float)W_IMG - 1.0f) * 0.5f;
    float py  = ((ph1*pwn + 1.0f) * (float)H_IMG - 1.0f) * 0.5f;

    float op = valid ? (1.0f / (1.0f + expf(-opa[i]))) : 0.0f;
    float cr = 1.0f / (1.0f + expf(-col[3*i]));
    float cg = 1.0f / (1.0f + expf(-col[3*i+1]));
    float cb = 1.0f / (1.0f + expf(-col[3*i+2]));

    g_p0[i]  = make_float4(px, py, A2, Bq);
    g_p1[i]  = make_float4(C2, op, cr, cg);
    g_p2[i]  = make_float2(cb, cullR);
    g_key[i] = ((unsigned long long)fkey(tz) << 32) | (unsigned)i;

    out[3*HW + i]      = radii;
    out[3*HW + NG + i] = tz;
}

// ---------------- 2) O(N^2) rank sort (stable, tie-free keys) ----------------
// 32 blocks x 256 threads; 4 threads per gaussian, each scans keys j%4==sub.
__global__ void __launch_bounds__(256) k_rank()
{
    __shared__ unsigned long long sk[NG];
    int tid = threadIdx.x;
    for (int i = tid; i < NG; i += 256) sk[i] = g_key[i];
    __syncthreads();

    int gt  = blockIdx.x * 256 + tid;
    int gi  = gt >> 2;
    int sub = gt & 3;
    unsigned long long ki = sk[gi];

    int rk = 0;
#pragma unroll 8
    for (int it = 0; it < NG/4; it++) {
        rk += (sk[4*it + sub] < ki) ? 1 : 0;
    }
    rk += __shfl_xor_sync(0xffffffffu, rk, 1);
    rk += __shfl_xor_sync(0xffffffffu, rk, 2);

    if (sub == 0) {
        g_s0[rk] = g_p0[gi];
        g_s1[rk] = g_p1[gi];
        g_s2[rk] = g_p2[gi];
    }
}

// ---------------- 3) tiled blend: one 16x16 tile per block -------------------
__global__ void __launch_bounds__(256) k_blend(float* __restrict__ out)
{
    __shared__ float4 b0[256];
    __shared__ float4 b1[256];
    __shared__ float  b2[256];
    __shared__ int    wcnt[8];

    int tid  = threadIdx.x;
    int wid  = tid >> 5;
    int lane = tid & 31;

    int tx = blockIdx.x & 7;        // 8x8 tiles of 16x16
    int ty = blockIdx.x >> 3;
    int pxi = tx * 16 + (tid & 15);
    int pyi = ty * 16 + (tid >> 4);
    float x = (float)pxi;
    float y = (float)pyi;
    float x0 = (float)(tx * 16), x1 = x0 + 15.f;
    float y0 = (float)(ty * 16), y1 = y0 + 15.f;

    float r = 0.f, g = 0.f, b = 0.f, T = 1.f;

    for (int chunk = 0; chunk < NCHUNK; chunk++) {
        int i = chunk * 256 + tid;
        float4 a0 = g_s0[i];
        float4 a1 = g_s1[i];
        float2 e2 = g_s2[i];
        float  R  = e2.y;

        bool pred = (R > 0.f) &&
                    (a0.x + R >= x0) && (a0.x - R <= x1) &&
                    (a0.y + R >= y0) && (a0.y - R <= y1);

        unsigned m = __ballot_sync(0xffffffffu, pred);
        if (lane == 0) wcnt[wid] = __popc(m);
        __syncthreads();

        int base = 0, cnt = 0;
#pragma unroll
        for (int w2 = 0; w2 < 8; w2++) {
            int c = wcnt[w2];
            if (w2 < wid) base += c;
            cnt += c;
        }
        if (pred) {
            int pos = base + __popc(m & ((1u << lane) - 1u));
            b0[pos] = a0;
            b1[pos] = a1;
            b2[pos] = e2.x;
        }
        __syncthreads();

        for (int n = 0; n < cnt; n++) {
            float4 c0 = b0[n];
            float4 c1 = b1[n];
            float  cb = b2[n];
            float dx = x - c0.x;
            float dy = y - c0.y;
            float pw = fmaf(c0.z*dx, dx, fmaf(c1.x*dy, dy, (c0.w*dx)*dy));
            float ee = ex2(pw);
            float al = fminf(c1.y * ee, 0.99f);
            float w  = ((pw <= 0.0f) && (al >= 0.0039215686f)) ? T * al : 0.0f;
            r = fmaf(w, c1.z, r);
            g = fmaf(w, c1.w, g);
            b = fmaf(w, cb,  b);
            T -= w;
        }
        // barrier for smem reuse + block-uniform saturation early-out
        if (__syncthreads_and(T < 1e-4f)) break;
    }

    int p = pyi * W_IMG + pxi;
    out[p]        = r;
    out[HW + p]   = g;
    out[2*HW + p] = b;
}

// ---------------- launch -----------------------------------------------------
extern "C" void kernel_launch(void* const* d_in, const int* in_sizes, int n_in,
                              void* d_out, int out_size)
{
    const float* pts  = (const float*)d_in[0];
    const float* scl  = (const float*)d_in[1];
    const float* col  = (const float*)d_in[2];
    const float* opa  = (const float*)d_in[3];
    const float* rot  = (const float*)d_in[4];
    const float* view = (const float*)d_in[5];
    const float* proj = (const float*)d_in[6];
    float* out = (float*)d_out;

    k_prep <<<NG/256, 256>>>(pts, scl, col, opa, rot, view, proj, out);
    k_rank <<<32, 256>>>();
    k_blend<<<64, 256>>>(out);
}

// round 3
// speedup vs baseline: 2.1541x; 1.4020x over previous
#include <cuda_runtime.h>
#include <cuda_bf16.h>

#define NG    2048
#define W_IMG 128
#define H_IMG 128
#define HW    16384
#define NCHUNK 8          // 2048 / 256 depth chunks

// ---------------- scratch (static device globals) ----------------------------
__device__ float4 g_p0[NG], g_p1[NG];          // unsorted packed params
__device__ float2 g_p2[NG];                    // (cb, cullR)
__device__ unsigned long long g_key[NG];       // monotone depth key | index
__device__ float4 g_s0[NG], g_s1[NG];          // depth-sorted
__device__ float2 g_s2[NG];

__device__ __forceinline__ float ex2(float x) {
    float y;
    asm("ex2.approx.f32 %0, %1;" : "=f"(y) : "f"(x));
    return y;
}
__device__ __forceinline__ float frcp(float x) {
    float y;
    asm("rcp.approx.f32 %0, %1;" : "=f"(y) : "f"(x));
    return y;
}
__device__ __forceinline__ float sig_ap(float x) {     // sigmoid, approx
    return frcp(1.0f + ex2(-1.4426950408889634f * x));
}
__device__ __forceinline__ float exp_ap(float x) {     // exp, approx
    return ex2(1.4426950408889634f * x);
}

// monotone map float -> uint (total order matches float <)
__device__ __forceinline__ unsigned fkey(float f) {
    unsigned u = __float_as_uint(f);
    return (u & 0x80000000u) ? ~u : (u | 0x80000000u);
}

// ---------------- 1) per-gaussian preprocess --------------------------------
__global__ void __launch_bounds__(64) k_prep(
        const float* __restrict__ pts, const float* __restrict__ scl,
        const float* __restrict__ col, const float* __restrict__ opa,
        const float* __restrict__ rot, const float* __restrict__ view,
        const float* __restrict__ proj, float* __restrict__ out)
{
    int i = blockIdx.x * 64 + threadIdx.x;
    if (i >= NG) return;

    float v[16], pr[16];
#pragma unroll
    for (int k = 0; k < 16; k++) v[k]  = view[k];
#pragma unroll
    for (int k = 0; k < 16; k++) pr[k] = proj[k];

    float p0 = pts[3*i], p1 = pts[3*i+1], p2 = pts[3*i+2];

    // camera-space point
    float t0 = v[0]*p0 + v[1]*p1 + v[2]*p2  + v[3];
    float t1 = v[4]*p0 + v[5]*p1 + v[6]*p2  + v[7];
    float tz = v[8]*p0 + v[9]*p1 + v[10]*p2 + v[11];

    // quaternion -> rotation
    float q0 = rot[4*i], q1 = rot[4*i+1], q2 = rot[4*i+2], q3 = rot[4*i+3];
    float qn = rsqrtf(q0*q0 + q1*q1 + q2*q2 + q3*q3);
    q0 *= qn; q1 *= qn; q2 *= qn; q3 *= qn;
    float R0 = 1.f - 2.f*(q2*q2 + q3*q3), R1 = 2.f*(q1*q2 - q0*q3), R2 = 2.f*(q1*q3 + q0*q2);
    float R3 = 2.f*(q1*q2 + q0*q3), R4 = 1.f - 2.f*(q1*q1 + q3*q3), R5 = 2.f*(q2*q3 - q0*q1);
    float R6 = 2.f*(q1*q3 - q0*q2), R7 = 2.f*(q2*q3 + q0*q1), R8 = 1.f - 2.f*(q1*q1 + q2*q2);

    float s0 = exp_ap(scl[3*i]), s1 = exp_ap(scl[3*i+1]), s2 = exp_ap(scl[3*i+2]);
    float M0 = R0*s0, M1 = R1*s1, M2 = R2*s2;
    float M3 = R3*s0, M4 = R4*s1, M5 = R5*s2;
    float M6 = R6*s0, M7 = R7*s1, M8 = R8*s2;

    const float fx = 64.f, fy = 64.f;
    float invz = frcp(tz);
    float txz = fminf(fmaxf(t0*invz, -1.3f), 1.3f) * tz;
    float tyz = fminf(fmaxf(t1*invz, -1.3f), 1.3f) * tz;
    float J00 = fx*invz, J02 = -fx*txz*invz*invz;
    float J11 = fy*invz, J12 = -fy*tyz*invz*invz;

    float T00 = J00*v[0] + J02*v[8],  T01 = J00*v[1] + J02*v[9],  T02 = J00*v[2] + J02*v[10];
    float T10 = J11*v[4] + J12*v[8],  T11 = J11*v[5] + J12*v[9],  T12 = J11*v[6] + J12*v[10];

    float X00 = T00*M0 + T01*M3 + T02*M6;
    float X01 = T00*M1 + T01*M4 + T02*M7;
    float X02 = T00*M2 + T01*M5 + T02*M8;
    float X10 = T10*M0 + T11*M3 + T12*M6;
    float X11 = T10*M1 + T11*M4 + T12*M7;
    float X12 = T10*M2 + T11*M5 + T12*M8;

    float a = X00*X00 + X01*X01 + X02*X02 + 0.3f;
    float b = X00*X10 + X01*X11 + X02*X12;
    float c = X10*X10 + X11*X11 + X12*X12 + 0.3f;

    float det   = a*c - b*b;
    bool  valid = (tz > 0.2f) && (det > 0.0f);
    float det_s = (det > 0.0f) ? det : 1.0f;
    float idet  = frcp(det_s);

    const float L2E = 1.4426950408889634f;
    float A2 = -0.5f * c * idet * L2E;
    float C2 = -0.5f * a * idet * L2E;
    float Bq =         b * idet * L2E;

    float mid   = 0.5f * (a + c);
    float slam  = sqrtf(fmaxf(mid*mid - det, 0.1f) * 0.0f + fmaxf(mid*mid - det, 0.1f)); // exact sqrt
    float lam   = mid + slam;
    float sq    = sqrtf(lam);                       // exact (feeds ceil)
    float radii = valid ? ceilf(3.0f * sq) : 0.0f;
    // exact cull radius: alpha<1/255 guaranteed beyond 3.3292*sqrt(lam) since op<1
    float cullR = valid ? 3.3294f * sq : 0.0f;

    float fr0[4], fr1[4], fr3[4];
#pragma unroll
    for (int cc = 0; cc < 4; cc++) {
        fr0[cc] = pr[0]*v[cc]  + pr[1]*v[4+cc]  + pr[2]*v[8+cc]  + pr[3]*v[12+cc];
        fr1[cc] = pr[4]*v[cc]  + pr[5]*v[4+cc]  + pr[6]*v[8+cc]  + pr[7]*v[12+cc];
        fr3[cc] = pr[12]*v[cc] + pr[13]*v[4+cc] + pr[14]*v[8+cc] + pr[15]*v[12+cc];
    }
    float ph0 = fr0[0]*p0 + fr0[1]*p1 + fr0[2]*p2 + fr0[3];
    float ph1 = fr1[0]*p0 + fr1[1]*p1 + fr1[2]*p2 + fr1[3];
    float ph3 = fr3[0]*p0 + fr3[1]*p1 + fr3[2]*p2 + fr3[3];
    float pwn = frcp(ph3 + 1e-7f);
    float px  = ((ph0*pwn + 1.0f) * (float)W_IMG - 1.0f) * 0.5f;
    float py  = ((ph1*pwn + 1.0f) * (float)H_IMG - 1.0f) * 0.5f;

    float op = valid ? sig_ap(opa[i]) : 0.0f;
    float cr = sig_ap(col[3*i]);
    float cg = sig_ap(col[3*i+1]);
    float cb = sig_ap(col[3*i+2]);

    g_p0[i]  = make_float4(px, py, A2, Bq);
    g_p1[i]  = make_float4(C2, op, cr, cg);
    g_p2[i]  = make_float2(cb, cullR);
    g_key[i] = ((unsigned long long)fkey(tz) << 32) | (unsigned)i;

    out[3*HW + i]      = radii;
    out[3*HW + NG + i] = tz;
}

// ---------------- 2) O(N^2) rank sort (stable, tie-free keys) ----------------
// 64 blocks x 256 threads; 8 threads per gaussian, each scans keys j%8==sub.
__global__ void __launch_bounds__(256) k_rank()
{
    __shared__ unsigned long long sk[NG];
    int tid = threadIdx.x;
    for (int i = tid; i < NG; i += 256) sk[i] = g_key[i];
    __syncthreads();

    int gt  = blockIdx.x * 256 + tid;
    int gi  = gt >> 3;
    int sub = gt & 7;
    unsigned long long ki = sk[gi];

    int rk = 0;
#pragma unroll 8
    for (int it = 0; it < NG/8; it++) {
        rk += (sk[8*it + sub] < ki) ? 1 : 0;
    }
    rk += __shfl_xor_sync(0xffffffffu, rk, 1);
    rk += __shfl_xor_sync(0xffffffffu, rk, 2);
    rk += __shfl_xor_sync(0xffffffffu, rk, 4);

    if (sub == 0) {
        g_s0[rk] = g_p0[gi];
        g_s1[rk] = g_p1[gi];
        g_s2[rk] = g_p2[gi];
    }
}

// ---------------- 3) tiled blend: one 16x8 tile per block --------------------
__global__ void __launch_bounds__(128) k_blend(float* __restrict__ out)
{
    __shared__ float4 b0[256];
    __shared__ float4 b1[256];
    __shared__ float  b2[256];
    __shared__ int    wcnt[8];      // [0..3]=half0 per warp, [4..7]=half1

    int tid  = threadIdx.x;         // 128
    int wid  = tid >> 5;            // 0..3
    int lane = tid & 31;

    int tx = blockIdx.x & 7;        // 8 tiles across, 16 px wide
    int ty = blockIdx.x >> 3;       // 16 tiles down,  8 px tall
    int pxi = tx * 16 + (tid & 15);
    int pyi = ty * 8  + (tid >> 4);
    float x = (float)pxi;
    float y = (float)pyi;
    float x0 = (float)(tx * 16), x1 = x0 + 15.f;
    float y0 = (float)(ty * 8),  y1 = y0 + 7.f;

    float r = 0.f, g = 0.f, b = 0.f, T = 1.f;

    // prefetch chunk 0 (two halves of 128)
    float4 A0 = g_s0[tid],       A1 = g_s1[tid];       float2 A2v = g_s2[tid];
    float4 B0 = g_s0[128 + tid], B1 = g_s1[128 + tid]; float2 B2v = g_s2[128 + tid];

    for (int chunk = 0; chunk < NCHUNK; chunk++) {
        float Ra = A2v.y, Rb = B2v.y;
        bool p0 = (Ra > 0.f) && (A0.x + Ra >= x0) && (A0.x - Ra <= x1)
                             && (A0.y + Ra >= y0) && (A0.y - Ra <= y1);
        bool p1 = (Rb > 0.f) && (B0.x + Rb >= x0) && (B0.x - Rb <= x1)
                             && (B0.y + Rb >= y0) && (B0.y - Rb <= y1);

        unsigned m0 = __ballot_sync(0xffffffffu, p0);
        unsigned m1 = __ballot_sync(0xffffffffu, p1);
        if (lane == 0) { wcnt[wid] = __popc(m0); wcnt[4 + wid] = __popc(m1); }
        __syncthreads();

        int c0 = wcnt[0], c1 = wcnt[1], c2 = wcnt[2], c3 = wcnt[3];
        int c4 = wcnt[4], c5 = wcnt[5], c6 = wcnt[6], c7 = wcnt[7];
        int tot0 = c0 + c1 + c2 + c3;
        int cnt  = tot0 + c4 + c5 + c6 + c7;
        int pre0 = (wid > 0 ? c0 : 0) + (wid > 1 ? c1 : 0) + (wid > 2 ? c2 : 0);
        int pre1 = tot0 + (wid > 0 ? c4 : 0) + (wid > 1 ? c5 : 0) + (wid > 2 ? c6 : 0);

        if (p0) {
            int pos = pre0 + __popc(m0 & ((1u << lane) - 1u));
            b0[pos] = A0; b1[pos] = A1; b2[pos] = A2v.x;
        }
        if (p1) {
            int pos = pre1 + __popc(m1 & ((1u << lane) - 1u));
            b0[pos] = B0; b1[pos] = B1; b2[pos] = B2v.x;
        }
        __syncthreads();

        // prefetch next chunk while inner loop runs
        if (chunk < NCHUNK - 1) {
            int nb = (chunk + 1) * 256;
            A0 = g_s0[nb + tid];       A1 = g_s1[nb + tid];       A2v = g_s2[nb + tid];
            B0 = g_s0[nb + 128 + tid]; B1 = g_s1[nb + 128 + tid]; B2v = g_s2[nb + 128 + tid];
        }

#pragma unroll 4
        for (int n = 0; n < cnt; n++) {
            float4 c0v = b0[n];
            float4 c1v = b1[n];
            float  cbv = b2[n];
            float dx = x - c0v.x;
            float dy = y - c0v.y;
            float pw = fmaf(c0v.z*dx, dx, fmaf(c1v.x*dy, dy, (c0v.w*dx)*dy));
            float ee = ex2(pw);
            float al = fminf(c1v.y * ee, 0.99f);
            float w  = ((pw <= 0.0f) && (al >= 0.0039215686f)) ? T * al : 0.0f;
            r = fmaf(w, c1v.z, r);
            g = fmaf(w, c1v.w, g);
            b = fmaf(w, cbv,  b);
            T -= w;
        }
        // barrier for smem reuse + block-uniform saturation early-out
        if (__syncthreads_and(T < 1e-4f)) break;
    }

    int p = pyi * W_IMG + pxi;
    out[p]        = r;
    out[HW + p]   = g;
    out[2*HW + p] = b;
}

// ---------------- launch -----------------------------------------------------
extern "C" void kernel_launch(void* const* d_in, const int* in_sizes, int n_in,
                              void* d_out, int out_size)
{
    const float* pts  = (const float*)d_in[0];
    const float* scl  = (const float*)d_in[1];
    const float* col  = (const float*)d_in[2];
    const float* opa  = (const float*)d_in[3];
    const float* rot  = (const float*)d_in[4];
    const float* view = (const float*)d_in[5];
    const float* proj = (const float*)d_in[6];
    float* out = (float*)d_out;

    k_prep <<<NG/64, 64>>>(pts, scl, col, opa, rot, view, proj, out);
    k_rank <<<64, 256>>>();
    k_blend<<<128, 128>>>(out);
}